// round 2
// baseline (speedup 1.0000x reference)
#include <cuda_runtime.h>
#include <math.h>

#define BB 128   // batch
#define II 512   // input
#define TT 256   // time
#define HH 1024  // hidden
#define GG (4*HH) // 4096 gate width

// Scratch (static __device__ allocations are the sanctioned scratch mechanism).
// x_proj layout: [t][b][g]  (g contiguous -> coalesced reads in recurrent phase)
__device__ float4 g_xproj4[(size_t)TT * BB * GG / 4];   // 512 MB
__device__ float4 g_h4[2][BB * HH / 4];                 // double-buffered h
__device__ unsigned g_cnt;
__device__ unsigned g_gen;

// ---------------------------------------------------------------------------
// Phase 1: x_proj[t][b][g] = sum_i W_ih[g][i] * x[b][i][t] + b_ih[g] + b_hh[g]
// Per-b NN GEMM: A = W_ih [4096 x 512] (K contig), B = x_b [512 x 256] (t contig)
// Tile 64(g) x 64(t), BK=16, 256 threads, 4x4 micro-tile.
// ---------------------------------------------------------------------------
__global__ __launch_bounds__(256) void xproj_kernel(
    const float* __restrict__ x,
    const float* __restrict__ Wih,
    const float* __restrict__ bih,
    const float* __restrict__ bhh)
{
    __shared__ float As[16][68];  // [k][g_local]
    __shared__ float Bs[16][68];  // [k][t_local]

    const int b  = blockIdx.z;
    const int g0 = blockIdx.x * 64;
    const int t0 = blockIdx.y * 64;
    const int tx = threadIdx.x;
    const int tm = tx & 15;   // g micro index (m = tm*4)
    const int tn = tx >> 4;   // t micro index (n = tn*4)

    float acc[4][4];
#pragma unroll
    for (int i = 0; i < 4; i++)
#pragma unroll
        for (int jj = 0; jj < 4; jj++) acc[i][jj] = 0.f;

    const int arow = tx >> 2;          // 0..63 (g rows)
    const int acg  = tx & 3;           // k group
    const int brow = tx >> 4;          // 0..15 (k rows)
    const int bcg  = tx & 15;          // t group
    const size_t xbase = (size_t)b * II * TT;

    for (int k0 = 0; k0 < II; k0 += 16) {
        // Load A tile: W_ih[g0+arow][k0 + acg*4 .. +3], store transposed [k][m]
        float4 av = *(const float4*)&Wih[(size_t)(g0 + arow) * II + k0 + (acg << 2)];
        As[(acg << 2) + 0][arow] = av.x;
        As[(acg << 2) + 1][arow] = av.y;
        As[(acg << 2) + 2][arow] = av.z;
        As[(acg << 2) + 3][arow] = av.w;
        // Load B tile: x[b][k0+brow][t0 + bcg*4 .. +3]   (t contiguous)
        float4 bv = *(const float4*)&x[xbase + (size_t)(k0 + brow) * TT + t0 + (bcg << 2)];
        *(float4*)&Bs[brow][bcg << 2] = bv;
        __syncthreads();

#pragma unroll
        for (int k = 0; k < 16; k++) {
            float4 a  = *(const float4*)&As[k][tm << 2];
            float4 b4 = *(const float4*)&Bs[k][tn << 2];
            acc[0][0] += a.x * b4.x; acc[0][1] += a.x * b4.y; acc[0][2] += a.x * b4.z; acc[0][3] += a.x * b4.w;
            acc[1][0] += a.y * b4.x; acc[1][1] += a.y * b4.y; acc[1][2] += a.y * b4.z; acc[1][3] += a.y * b4.w;
            acc[2][0] += a.z * b4.x; acc[2][1] += a.z * b4.y; acc[2][2] += a.z * b4.z; acc[2][3] += a.z * b4.w;
            acc[3][0] += a.w * b4.x; acc[3][1] += a.w * b4.y; acc[3][2] += a.w * b4.z; acc[3][3] += a.w * b4.w;
        }
        __syncthreads();
    }

    // bias (added once here; reference adds b_ih + b_hh into x_proj)
    float bsv[4];
#pragma unroll
    for (int mi = 0; mi < 4; mi++) {
        int g = g0 + (tm << 2) + mi;
        bsv[mi] = bih[g] + bhh[g];
    }

    float* xp = (float*)g_xproj4;
#pragma unroll
    for (int ni = 0; ni < 4; ni++) {
        int t = t0 + (tn << 2) + ni;
        float4 v;
        v.x = acc[0][ni] + bsv[0];
        v.y = acc[1][ni] + bsv[1];
        v.z = acc[2][ni] + bsv[2];
        v.w = acc[3][ni] + bsv[3];
        *(float4*)&xp[(size_t)t * BB * GG + (size_t)b * GG + g0 + (tm << 2)] = v;
    }
}

// ---------------------------------------------------------------------------
// Software grid barrier (all CTAs co-resident: grid=128 <= 148 SMs, 1 CTA/SM)
// ---------------------------------------------------------------------------
__device__ __forceinline__ void grid_sync()
{
    __syncthreads();
    if (threadIdx.x == 0) {
        __threadfence();
        unsigned gen = *(volatile unsigned*)&g_gen;
        if (atomicAdd(&g_cnt, 1) == gridDim.x - 1) {
            g_cnt = 0;
            __threadfence();
            atomicAdd(&g_gen, 1);
        } else {
            while (*(volatile unsigned*)&g_gen == gen) { }
        }
        __threadfence();
    }
    __syncthreads();
}

// ---------------------------------------------------------------------------
// Phase 2: persistent recurrent kernel. CTA j owns hidden cols [8j, 8j+8).
// Per step: GEMM tile gates[128 x 32] (cols = {q*1024 + 8j + nn}), K=1024,
// then the LSTM cell update for its 128x8 slice. c lives in SMEM per-CTA.
// ---------------------------------------------------------------------------
__global__ __launch_bounds__(256) void lstm_kernel(
    const float* __restrict__ Whh,
    float* __restrict__ out)
{
    __shared__ float As[16][132];     // [k][m]   h tile transposed
    __shared__ float Bs[16][36];      // [k][ln]  W tile transposed
    __shared__ float gbuf[128][33];   // gates [b][ln]
    __shared__ float c_s[128][8];     // cell state slice

    const int j  = blockIdx.x;        // 0..127
    const int tx = threadIdx.x;
    const int tm = tx & 31;           // m = tm*4 (batch rows)
    const int tn = tx >> 5;           // ln = tn*4 (gate cols 0..31)

    float* h0 = (float*)g_h4[0];
    float* h1 = (float*)g_h4[1];

    // init: zero c slice and our columns of h buffer 0
#pragma unroll
    for (int r = 0; r < 4; r++) {
        int cid = tx + 256 * r;       // 0..1023
        int b = cid >> 3, nn = cid & 7;
        c_s[b][nn] = 0.f;
        h0[b * HH + (j << 3) + nn] = 0.f;
    }
    grid_sync();

    const float* xpall = (const float*)g_xproj4;

    for (int t = 0; t < TT; t++) {
        const float* hr = (t & 1) ? h1 : h0;
        float*       hw = (t & 1) ? h0 : h1;

        float acc[4][4];
#pragma unroll
        for (int i = 0; i < 4; i++)
#pragma unroll
            for (int jj = 0; jj < 4; jj++) acc[i][jj] = 0.f;

        for (int k0 = 0; k0 < HH; k0 += 16) {
            // A tile: h[128 x 16] -> As[k][m]; 512 float4 loads, 2/thread
#pragma unroll
            for (int r = 0; r < 2; r++) {
                int idx = tx + 256 * r;        // 0..511
                int row = idx >> 2;            // b 0..127
                int cg  = idx & 3;
                float4 v = *(const float4*)&hr[row * HH + k0 + (cg << 2)];
                As[(cg << 2) + 0][row] = v.x;
                As[(cg << 2) + 1][row] = v.y;
                As[(cg << 2) + 2][row] = v.z;
                As[(cg << 2) + 3][row] = v.w;
            }
            // B tile: W_hh rows for our 32 gate-cols -> Bs[k][ln]
            if (tx < 128) {
                int ln = tx >> 2;              // 0..31
                int cg = tx & 3;
                int g  = ((ln >> 3) << 10) + (j << 3) + (ln & 7);
                float4 v = *(const float4*)&Whh[(size_t)g * HH + k0 + (cg << 2)];
                Bs[(cg << 2) + 0][ln] = v.x;
                Bs[(cg << 2) + 1][ln] = v.y;
                Bs[(cg << 2) + 2][ln] = v.z;
                Bs[(cg << 2) + 3][ln] = v.w;
            }
            __syncthreads();

#pragma unroll
            for (int k = 0; k < 16; k++) {
                float4 a  = *(const float4*)&As[k][tm << 2];
                float4 b4 = *(const float4*)&Bs[k][tn << 2];
                acc[0][0] += a.x * b4.x; acc[0][1] += a.x * b4.y; acc[0][2] += a.x * b4.z; acc[0][3] += a.x * b4.w;
                acc[1][0] += a.y * b4.x; acc[1][1] += a.y * b4.y; acc[1][2] += a.y * b4.z; acc[1][3] += a.y * b4.w;
                acc[2][0] += a.z * b4.x; acc[2][1] += a.z * b4.y; acc[2][2] += a.z * b4.z; acc[2][3] += a.z * b4.w;
                acc[3][0] += a.w * b4.x; acc[3][1] += a.w * b4.y; acc[3][2] += a.w * b4.z; acc[3][3] += a.w * b4.w;
            }
            __syncthreads();
        }

        // epilogue: add x_proj, stash gates to smem
        const float* xp = xpall + (size_t)t * BB * GG;
        const int ln0 = tn << 2;
        const int gbase = ((ln0 >> 3) << 10) + (j << 3) + (ln0 & 7); // 4 consecutive g
#pragma unroll
        for (int mi = 0; mi < 4; mi++) {
            int m = (tm << 2) + mi;
            float4 xv = *(const float4*)&xp[(size_t)m * GG + gbase];
            gbuf[m][ln0 + 0] = acc[mi][0] + xv.x;
            gbuf[m][ln0 + 1] = acc[mi][1] + xv.y;
            gbuf[m][ln0 + 2] = acc[mi][2] + xv.z;
            gbuf[m][ln0 + 3] = acc[mi][3] + xv.w;
        }
        __syncthreads();

        // cell update: 1024 cells, 4/thread
#pragma unroll
        for (int r = 0; r < 4; r++) {
            int cid = tx + 256 * r;
            int b = cid >> 3, nn = cid & 7;
            float gi = gbuf[b][nn];
            float gf = gbuf[b][8 + nn];
            float gg = gbuf[b][16 + nn];
            float go = gbuf[b][24 + nn];
            float iv = 1.f / (1.f + __expf(-gi));
            float fv = 1.f / (1.f + __expf(-gf));
            float gv = tanhf(gg);
            float ov = 1.f / (1.f + __expf(-go));
            float c  = fv * c_s[b][nn] + iv * gv;
            c_s[b][nn] = c;
            hw[b * HH + (j << 3) + nn] = ov * tanhf(c);
        }
        grid_sync();
    }

    // final h is in buffer 0 (t=255 wrote (255+1)&1 = 0)
#pragma unroll
    for (int r = 0; r < 4; r++) {
        int cid = tx + 256 * r;
        int b = cid >> 3, nn = cid & 7;
        out[b * HH + (j << 3) + nn] = h0[b * HH + (j << 3) + nn];
    }
}

extern "C" void kernel_launch(void* const* d_in, const int* in_sizes, int n_in,
                              void* d_out, int out_size)
{
    const float* x   = (const float*)d_in[0];
    const float* Wih = (const float*)d_in[1];
    const float* Whh = (const float*)d_in[2];
    const float* bih = (const float*)d_in[3];
    const float* bhh = (const float*)d_in[4];
    float* out = (float*)d_out;

    dim3 g1(GG / 64, TT / 64, BB);   // 64 x 4 x 128
    xproj_kernel<<<g1, 256>>>(x, Wih, bih, bhh);
    lstm_kernel<<<128, 256>>>(Whh, out);
}

// round 4
// speedup vs baseline: 2.1642x; 2.1642x over previous
#include <cuda_runtime.h>
#include <cuda_bf16.h>
#include <cstdint>
#include <math.h>

#define BB 128
#define II 512
#define TT 256
#define HH 1024
#define GG (4*HH)

// ---------------- scratch -----------------------------------------------
__device__ float4 g_xproj4[(size_t)TT * BB * GG / 4];       // [t][b][g]
__device__ uint4  g_Whl4[2][(size_t)GG * HH / 8];           // bf16 hi/lo W_hh
__device__ uint4  g_hbf4[2][2][(size_t)BB * HH / 8];        // [dbuf][hi/lo] bf16
__device__ unsigned g_cnt, g_gen;

// ---------------- smem layout (lstm kernel, dynamic) --------------------
#define SM_WHI 0
#define SM_WLO 66048                       // 32 rows * 1032 bf16 * 2B
#define SM_A(buf, hl) (132096 + (buf)*36864 + (hl)*18432)   // 128 x 72 bf16
#define SM_TOT 205824

__device__ __forceinline__ uint32_t smem_u32(const void* p) {
    uint32_t a;
    asm("{ .reg .u64 t; cvta.to.shared.u64 t, %1; cvt.u32.u64 %0, t; }" : "=r"(a) : "l"(p));
    return a;
}

#define CP16(sa, ga) \
    asm volatile("cp.async.cg.shared.global [%0], [%1], 16;" :: "r"(sa), "l"(ga) : "memory")
#define CP_COMMIT() asm volatile("cp.async.commit_group;" ::: "memory")
#define CP_WAIT1()  asm volatile("cp.async.wait_group 1;" ::: "memory")
#define CP_WAIT0()  asm volatile("cp.async.wait_group 0;" ::: "memory")

#define LDSM4(r, a) \
    asm volatile("ldmatrix.sync.aligned.m8n8.x4.shared.b16 {%0,%1,%2,%3}, [%4];" \
        : "=r"((r)[0]), "=r"((r)[1]), "=r"((r)[2]), "=r"((r)[3]) : "r"(a))
#define LDSM2(r, a) \
    asm volatile("ldmatrix.sync.aligned.m8n8.x2.shared.b16 {%0,%1}, [%2];" \
        : "=r"((r)[0]), "=r"((r)[1]) : "r"(a))

#define MMA(d, a, b) \
    asm volatile("mma.sync.aligned.m16n8k16.row.col.f32.bf16.bf16.f32 " \
        "{%0,%1,%2,%3}, {%4,%5,%6,%7}, {%8,%9}, {%0,%1,%2,%3};" \
        : "+f"((d)[0]), "+f"((d)[1]), "+f"((d)[2]), "+f"((d)[3]) \
        : "r"((a)[0]), "r"((a)[1]), "r"((a)[2]), "r"((a)[3]), "r"((b)[0]), "r"((b)[1]))

// ---------------------------------------------------------------------------
// Prep: split W_hh into bf16 hi/lo; zero initial h buffers
// ---------------------------------------------------------------------------
__global__ void prep_kernel(const float* __restrict__ Whh)
{
    size_t i = (size_t)blockIdx.x * blockDim.x + threadIdx.x;
    __nv_bfloat16* whi = (__nv_bfloat16*)g_Whl4[0];
    __nv_bfloat16* wlo = (__nv_bfloat16*)g_Whl4[1];
    if (i < (size_t)GG * HH) {
        float v = Whh[i];
        __nv_bfloat16 h = __float2bfloat16(v);
        whi[i] = h;
        wlo[i] = __float2bfloat16(v - __bfloat162float(h));
    }
    if (i < (size_t)BB * HH) {
        ((__nv_bfloat16*)g_hbf4[0][0])[i] = __float2bfloat16(0.f);
        ((__nv_bfloat16*)g_hbf4[0][1])[i] = __float2bfloat16(0.f);
    }
}

// ---------------------------------------------------------------------------
// Phase 1 (SIMT fp32): x_proj[t][b][g] = W_ih @ x + b_ih + b_hh
// ---------------------------------------------------------------------------
__global__ __launch_bounds__(256) void xproj_kernel(
    const float* __restrict__ x,
    const float* __restrict__ Wih,
    const float* __restrict__ bih,
    const float* __restrict__ bhh)
{
    __shared__ float As[16][68];
    __shared__ float Bs[16][68];

    const int b  = blockIdx.z;
    const int g0 = blockIdx.x * 64;
    const int t0 = blockIdx.y * 64;
    const int tx = threadIdx.x;
    const int tm = tx & 15;
    const int tn = tx >> 4;

    float acc[4][4];
#pragma unroll
    for (int i = 0; i < 4; i++)
#pragma unroll
        for (int jj = 0; jj < 4; jj++) acc[i][jj] = 0.f;

    const int arow = tx >> 2;
    const int acg  = tx & 3;
    const int brow = tx >> 4;
    const int bcg  = tx & 15;
    const size_t xbase = (size_t)b * II * TT;

    for (int k0 = 0; k0 < II; k0 += 16) {
        float4 av = *(const float4*)&Wih[(size_t)(g0 + arow) * II + k0 + (acg << 2)];
        As[(acg << 2) + 0][arow] = av.x;
        As[(acg << 2) + 1][arow] = av.y;
        As[(acg << 2) + 2][arow] = av.z;
        As[(acg << 2) + 3][arow] = av.w;
        float4 bv = *(const float4*)&x[xbase + (size_t)(k0 + brow) * TT + t0 + (bcg << 2)];
        *(float4*)&Bs[brow][bcg << 2] = bv;
        __syncthreads();

#pragma unroll
        for (int k = 0; k < 16; k++) {
            float4 a  = *(const float4*)&As[k][tm << 2];
            float4 b4 = *(const float4*)&Bs[k][tn << 2];
            acc[0][0] += a.x * b4.x; acc[0][1] += a.x * b4.y; acc[0][2] += a.x * b4.z; acc[0][3] += a.x * b4.w;
            acc[1][0] += a.y * b4.x; acc[1][1] += a.y * b4.y; acc[1][2] += a.y * b4.z; acc[1][3] += a.y * b4.w;
            acc[2][0] += a.z * b4.x; acc[2][1] += a.z * b4.y; acc[2][2] += a.z * b4.z; acc[2][3] += a.z * b4.w;
            acc[3][0] += a.w * b4.x; acc[3][1] += a.w * b4.y; acc[3][2] += a.w * b4.z; acc[3][3] += a.w * b4.w;
        }
        __syncthreads();
    }

    float bsv[4];
#pragma unroll
    for (int mi = 0; mi < 4; mi++) {
        int g = g0 + (tm << 2) + mi;
        bsv[mi] = bih[g] + bhh[g];
    }

    float* xp = (float*)g_xproj4;
#pragma unroll
    for (int ni = 0; ni < 4; ni++) {
        int t = t0 + (tn << 2) + ni;
        float4 v;
        v.x = acc[0][ni] + bsv[0];
        v.y = acc[1][ni] + bsv[1];
        v.z = acc[2][ni] + bsv[2];
        v.w = acc[3][ni] + bsv[3];
        *(float4*)&xp[(size_t)t * BB * GG + (size_t)b * GG + g0 + (tm << 2)] = v;
    }
}

// ---------------------------------------------------------------------------
__device__ __forceinline__ void grid_sync()
{
    __syncthreads();
    if (threadIdx.x == 0) {
        __threadfence();
        unsigned gen = *(volatile unsigned*)&g_gen;
        if (atomicAdd(&g_cnt, 1) == gridDim.x - 1) {
            g_cnt = 0;
            __threadfence();
            atomicAdd(&g_gen, 1);
        } else {
            while (*(volatile unsigned*)&g_gen == gen) { }
        }
        __threadfence();
    }
    __syncthreads();
}

// ---------------------------------------------------------------------------
// Phase 2: persistent HMMA recurrent kernel. CTA j owns h cols [8j,8j+8).
// N index n = q*8+nn -> gate col g = q*1024 + 8j + nn. W slice SMEM-resident.
// 3-pass hi/lo bf16: acc += Ahi*Bhi + Alo*Bhi + Ahi*Blo.
// ---------------------------------------------------------------------------
extern __shared__ char smem[];

__global__ __launch_bounds__(256, 1) void lstm_mma_kernel(float* __restrict__ out)
{
    const int tx   = threadIdx.x;
    const int wid  = tx >> 5;
    const int lane = tx & 31;
    const int j    = blockIdx.x;
    const uint32_t sb = smem_u32(smem);

    // ---- preload this CTA's W slice (32 gate rows x 1024, hi & lo) ----
    {
        const __nv_bfloat16* Whi = (const __nv_bfloat16*)g_Whl4[0];
        const __nv_bfloat16* Wlo = (const __nv_bfloat16*)g_Whl4[1];
        for (int idx = tx; idx < 32 * 128; idx += 256) {
            int row = idx >> 7, seg = idx & 127;        // seg: uint4 within row
            int g = ((row >> 3) << 10) + (j << 3) + (row & 7);
            *(uint4*)(smem + SM_WHI + row * 2064 + seg * 16) =
                *(const uint4*)(Whi + (size_t)g * HH + seg * 8);
            *(uint4*)(smem + SM_WLO + row * 2064 + seg * 16) =
                *(const uint4*)(Wlo + (size_t)g * HH + seg * 8);
        }
    }

    float c[4] = {0.f, 0.f, 0.f, 0.f};

    // lane-constant ldmatrix offsets
    const uint32_t aoff  = (uint32_t)((((wid << 4) + (lane & 15)) * 72 + ((lane >> 4) << 3)) * 2);
    const uint32_t wboff = (uint32_t)(((lane & 7) * 1032 + (((lane >> 3) & 1) << 3)) * 2);
    const uint32_t wb_hi = sb + SM_WHI + wboff;
    const uint32_t wb_lo = sb + SM_WLO + wboff;

    const float* xpall = (const float*)g_xproj4;
    __syncthreads();   // W smem ready

    for (int t = 0; t < TT; t++) {
        const __nv_bfloat16* hhi = (const __nv_bfloat16*)g_hbf4[t & 1][0];
        const __nv_bfloat16* hlo = (const __nv_bfloat16*)g_hbf4[t & 1][1];

        float acc[4][4];
#pragma unroll
        for (int q = 0; q < 4; q++)
#pragma unroll
            for (int e = 0; e < 4; e++) acc[q][e] = 0.f;

        // prologue: stage tile 0 into buf 0
        {
            const int row = tx >> 3, seg = tx & 7;   // base ids; 4 rows strides
#pragma unroll
            for (int r = 0; r < 4; r++) {
                int rr = row + (r << 5);             // tx + r*256 -> row = idx>>3
                uint32_t da = sb + SM_A(0, 0) + rr * 144 + seg * 16;
                uint32_t dl = sb + SM_A(0, 1) + rr * 144 + seg * 16;
                CP16(da, hhi + rr * HH + (seg << 3));
                CP16(dl, hlo + rr * HH + (seg << 3));
            }
            CP_COMMIT();
        }

        int buf = 0;
        for (int kt = 0; kt < 16; kt++) {
            if (kt < 15) {
                const int k0 = (kt + 1) << 6;
                const int row = tx >> 3, seg = tx & 7;
#pragma unroll
                for (int r = 0; r < 4; r++) {
                    int rr = row + (r << 5);
                    uint32_t da = sb + SM_A(buf ^ 1, 0) + rr * 144 + seg * 16;
                    uint32_t dl = sb + SM_A(buf ^ 1, 1) + rr * 144 + seg * 16;
                    CP16(da, hhi + rr * HH + k0 + (seg << 3));
                    CP16(dl, hlo + rr * HH + k0 + (seg << 3));
                }
                CP_COMMIT();
                CP_WAIT1();
            } else {
                CP_WAIT0();
            }
            __syncthreads();

            const uint32_t aHi = sb + SM_A(buf, 0) + aoff;
            const uint32_t aLo = sb + SM_A(buf, 1) + aoff;
#pragma unroll
            for (int ks = 0; ks < 4; ks++) {
                uint32_t ah[4], al[4];
                LDSM4(ah, aHi + ks * 32);
                LDSM4(al, aLo + ks * 32);
                const uint32_t kcol = (uint32_t)(((kt << 6) + (ks << 4)) * 2);
#pragma unroll
                for (int q = 0; q < 4; q++) {
                    uint32_t bh[2], bl[2];
                    LDSM2(bh, wb_hi + q * 16512 + kcol);
                    LDSM2(bl, wb_lo + q * 16512 + kcol);
                    MMA(acc[q], ah, bh);
                    MMA(acc[q], al, bh);
                    MMA(acc[q], ah, bl);
                }
            }
            __syncthreads();
            buf ^= 1;
        }

        // ---- epilogue: gates -> activations -> c,h (all in registers) ----
        const int r0  = (wid << 4) + (lane >> 2);
        const int nn0 = (lane & 3) << 1;
        const float* xpt = xpall + (size_t)t * BB * GG;
        const int nb = (t + 1) & 1;
        __nv_bfloat16* whi = (__nv_bfloat16*)g_hbf4[nb][0];
        __nv_bfloat16* wlo = (__nv_bfloat16*)g_hbf4[nb][1];

#pragma unroll
        for (int rh = 0; rh < 2; rh++) {
            const int row = r0 + (rh << 3);
            const float* bp = xpt + (size_t)row * GG + (j << 3) + nn0;
            float2 xi = *(const float2*)(bp);
            float2 xf = *(const float2*)(bp + 1024);
            float2 xg = *(const float2*)(bp + 2048);
            float2 xo = *(const float2*)(bp + 3072);
            float hv[2];
#pragma unroll
            for (int e = 0; e < 2; e++) {
                const int p = (rh << 1) + e;
                float gi = acc[0][p] + (e ? xi.y : xi.x);
                float gf = acc[1][p] + (e ? xf.y : xf.x);
                float gg = acc[2][p] + (e ? xg.y : xg.x);
                float go = acc[3][p] + (e ? xo.y : xo.x);
                float iv = 1.f / (1.f + __expf(-gi));
                float fv = 1.f / (1.f + __expf(-gf));
                float gv = tanhf(gg);
                float ov = 1.f / (1.f + __expf(-go));
                float cv = fv * c[p] + iv * gv;
                c[p] = cv;
                hv[e] = ov * tanhf(cv);
            }
            // pack + store h hi/lo
            __nv_bfloat16 a0 = __float2bfloat16(hv[0]);
            __nv_bfloat16 a1 = __float2bfloat16(hv[1]);
            __nv_bfloat16 l0 = __float2bfloat16(hv[0] - __bfloat162float(a0));
            __nv_bfloat16 l1 = __float2bfloat16(hv[1] - __bfloat162float(a1));
            uint32_t ph = (uint32_t)__bfloat16_as_ushort(a0) | ((uint32_t)__bfloat16_as_ushort(a1) << 16);
            uint32_t pl = (uint32_t)__bfloat16_as_ushort(l0) | ((uint32_t)__bfloat16_as_ushort(l1) << 16);
            *(uint32_t*)(whi + row * HH + (j << 3) + nn0) = ph;
            *(uint32_t*)(wlo + row * HH + (j << 3) + nn0) = pl;

            if (t == TT - 1) {
                float2 ov2; ov2.x = hv[0]; ov2.y = hv[1];
                *(float2*)(out + row * HH + (j << 3) + nn0) = ov2;
            }
        }
        grid_sync();
    }
}

// ---------------------------------------------------------------------------
extern "C" void kernel_launch(void* const* d_in, const int* in_sizes, int n_in,
                              void* d_out, int out_size)
{
    const float* x   = (const float*)d_in[0];
    const float* Wih = (const float*)d_in[1];
    const float* Whh = (const float*)d_in[2];
    const float* bih = (const float*)d_in[3];
    const float* bhh = (const float*)d_in[4];
    float* out = (float*)d_out;

    static int done = 0;
    if (!done) {
        cudaFuncSetAttribute(lstm_mma_kernel,
                             cudaFuncAttributeMaxDynamicSharedMemorySize, SM_TOT);
        done = 1;
    }

    prep_kernel<<<(int)(((size_t)GG * HH + 255) / 256), 256>>>(Whh);
    dim3 g1(GG / 64, TT / 64, BB);
    xproj_kernel<<<g1, 256>>>(x, Wih, bih, bhh);
    lstm_mma_kernel<<<128, 256, SM_TOT>>>(out);
}

// round 5
// speedup vs baseline: 3.4899x; 1.6126x over previous
#include <cuda_runtime.h>
#include <cuda_fp16.h>
#include <cstdint>
#include <math.h>

#define BB 128
#define II 512
#define TT 256
#define HH 1024
#define GG (4*HH)

// ---------------- scratch -----------------------------------------------
__device__ float4 g_xproj4[(size_t)TT * BB * GG / 4];       // [t][b][g] fp32
__device__ uint4  g_WhhH4[(size_t)GG * HH / 8];             // fp16 W_hh
__device__ uint4  g_WihH4[(size_t)GG * II / 8];             // fp16 W_ih
__device__ uint4  g_xT4[2][(size_t)BB * TT * II / 8];       // fp16 x^T hi/lo [b][t][k]
__device__ uint4  g_hbf4[2][2][(size_t)BB * HH / 8];        // h fp16 hi/lo, dbuf
__device__ float  g_bias[GG];
__device__ unsigned g_cnt, g_gen;

// ---------------- helpers -----------------------------------------------
__device__ __forceinline__ uint32_t smem_u32(const void* p) {
    uint32_t a;
    asm("{ .reg .u64 t; cvta.to.shared.u64 t, %1; cvt.u32.u64 %0, t; }" : "=r"(a) : "l"(p));
    return a;
}
#define CP16(sa, ga) \
    asm volatile("cp.async.cg.shared.global [%0], [%1], 16;" :: "r"(sa), "l"(ga) : "memory")
#define CP_COMMIT() asm volatile("cp.async.commit_group;" ::: "memory")
#define CP_WAIT1()  asm volatile("cp.async.wait_group 1;" ::: "memory")
#define CP_WAIT0()  asm volatile("cp.async.wait_group 0;" ::: "memory")

#define LDSM4(r, a) \
    asm volatile("ldmatrix.sync.aligned.m8n8.x4.shared.b16 {%0,%1,%2,%3}, [%4];" \
        : "=r"((r)[0]), "=r"((r)[1]), "=r"((r)[2]), "=r"((r)[3]) : "r"(a))
#define LDSM2(r, a) \
    asm volatile("ldmatrix.sync.aligned.m8n8.x2.shared.b16 {%0,%1}, [%2];" \
        : "=r"((r)[0]), "=r"((r)[1]) : "r"(a))
#define MMA(d, a, b) \
    asm volatile("mma.sync.aligned.m16n8k16.row.col.f32.f16.f16.f32 " \
        "{%0,%1,%2,%3}, {%4,%5,%6,%7}, {%8,%9}, {%0,%1,%2,%3};" \
        : "+f"((d)[0]), "+f"((d)[1]), "+f"((d)[2]), "+f"((d)[3]) \
        : "r"((a)[0]), "r"((a)[1]), "r"((a)[2]), "r"((a)[3]), "r"((b)[0]), "r"((b)[1]))

extern __shared__ char smem[];

// ---------------------------------------------------------------------------
// Prep kernels
// ---------------------------------------------------------------------------
__global__ void prep_whh(const float* __restrict__ Whh)
{
    size_t i = (size_t)blockIdx.x * blockDim.x + threadIdx.x;
    if (i < (size_t)GG * HH)
        ((__half*)g_WhhH4)[i] = __float2half_rn(Whh[i]);
    if (i < (size_t)BB * HH) {
        ((__half*)g_hbf4[0][0])[i] = __float2half(0.f);
        ((__half*)g_hbf4[0][1])[i] = __float2half(0.f);
    }
}
__global__ void prep_wih(const float* __restrict__ Wih,
                         const float* __restrict__ bih,
                         const float* __restrict__ bhh)
{
    size_t i = (size_t)blockIdx.x * blockDim.x + threadIdx.x;
    if (i < (size_t)GG * II)
        ((__half*)g_WihH4)[i] = __float2half_rn(Wih[i]);
    if (i < GG)
        g_bias[i] = bih[i] + bhh[i];
}
// transpose + fp16 hi/lo split: x[b][k][t] -> xT[b][t][k]
__global__ void prep_x(const float* __restrict__ x)
{
    __shared__ float s[32][33];
    const int b = blockIdx.z, k0 = blockIdx.y * 32, t0 = blockIdx.x * 32;
    const int tx = threadIdx.x, ty = threadIdx.y;   // 32 x 8
    const float* xb = x + (size_t)b * II * TT;
#pragma unroll
    for (int i = 0; i < 4; i++)
        s[ty + 8 * i][tx] = xb[(size_t)(k0 + ty + 8 * i) * TT + t0 + tx];
    __syncthreads();
    __half* xhi = (__half*)g_xT4[0];
    __half* xlo = (__half*)g_xT4[1];
    const size_t base = (size_t)b * TT * II;
#pragma unroll
    for (int i = 0; i < 4; i++) {
        float v = s[tx][ty + 8 * i];
        __half h = __float2half_rn(v);
        size_t o = base + (size_t)(t0 + ty + 8 * i) * II + k0 + tx;
        xhi[o] = h;
        xlo[o] = __float2half_rn(v - __half2float(h));
    }
}

// ---------------------------------------------------------------------------
// Phase 1: xproj via HMMA fp16 2-pass.
// A = xT[b][t][k] (M = t), B = W_ih[g][k] (N = g). Tiles 128x128, K=512.
// ---------------------------------------------------------------------------
#define SMX_AHI(bf) ((bf)*55296)
#define SMX_ALO(bf) ((bf)*55296 + 18432)
#define SMX_B(bf)   ((bf)*55296 + 36864)
#define SMX_TOT 110592

__global__ __launch_bounds__(256, 1) void xproj_mma(void)
{
    const int tx = threadIdx.x, wid = tx >> 5, lane = tx & 31;
    const int gt = blockIdx.x;   // g tile 0..31
    const int tt = blockIdx.y;   // t tile 0..1
    const int b  = blockIdx.z;
    const uint32_t sb = smem_u32(smem);
    const int wm = wid & 1, wn = wid >> 1;

    const __half* xhi = (const __half*)g_xT4[0] + (size_t)b * TT * II + (size_t)tt * 128 * II;
    const __half* xlo = (const __half*)g_xT4[1] + (size_t)b * TT * II + (size_t)tt * 128 * II;
    const __half* Wh  = (const __half*)g_WihH4 + (size_t)gt * 128 * II;

    float acc[4][4][4];
#pragma unroll
    for (int f = 0; f < 4; f++)
#pragma unroll
        for (int q = 0; q < 4; q++)
#pragma unroll
            for (int e = 0; e < 4; e++) acc[f][q][e] = 0.f;

    const int srow = tx >> 3, sseg = tx & 7;

    // prologue: chunk 0 -> buf 0
#pragma unroll
    for (int r = 0; r < 4; r++) {
        int row = srow + (r << 5);
        uint32_t d = row * 144 + sseg * 16;
        CP16(sb + SMX_AHI(0) + d, xhi + (size_t)row * II + (sseg << 3));
        CP16(sb + SMX_ALO(0) + d, xlo + (size_t)row * II + (sseg << 3));
        CP16(sb + SMX_B(0)   + d, Wh  + (size_t)row * II + (sseg << 3));
    }
    CP_COMMIT();

    int buf = 0;
    for (int kc = 0; kc < 8; kc++) {
        if (kc < 7) {
            const int k0 = (kc + 1) << 6;
#pragma unroll
            for (int r = 0; r < 4; r++) {
                int row = srow + (r << 5);
                uint32_t d = row * 144 + sseg * 16;
                CP16(sb + SMX_AHI(buf ^ 1) + d, xhi + (size_t)row * II + k0 + (sseg << 3));
                CP16(sb + SMX_ALO(buf ^ 1) + d, xlo + (size_t)row * II + k0 + (sseg << 3));
                CP16(sb + SMX_B(buf ^ 1)   + d, Wh  + (size_t)row * II + k0 + (sseg << 3));
            }
            CP_COMMIT();
            CP_WAIT1();
        } else {
            CP_WAIT0();
        }
        __syncthreads();

        const uint32_t aoff = (uint32_t)(((lane & 15) * 72 + ((lane >> 4) << 3)) * 2) + wm * 9216;
        const uint32_t aHi = sb + SMX_AHI(buf) + aoff;
        const uint32_t aLo = sb + SMX_ALO(buf) + aoff;
        const uint32_t bB  = sb + SMX_B(buf) + wn * 4608
                           + (uint32_t)(((lane & 7) * 72 + (((lane >> 3) & 1) << 3)) * 2);
#pragma unroll
        for (int ks = 0; ks < 4; ks++) {
            uint32_t bh[4][2];
#pragma unroll
            for (int q = 0; q < 4; q++)
                LDSM2(bh[q], bB + q * 1152 + ks * 32);
#pragma unroll
            for (int f = 0; f < 4; f++) {
                uint32_t ah[4], al[4];
                LDSM4(ah, aHi + f * 2304 + ks * 32);
                LDSM4(al, aLo + f * 2304 + ks * 32);
#pragma unroll
                for (int q = 0; q < 4; q++) {
                    MMA(acc[f][q], ah, bh[q]);
                    MMA(acc[f][q], al, bh[q]);
                }
            }
        }
        __syncthreads();
        buf ^= 1;
    }

    // epilogue: += bias, store to xp[t][b][g]
    float* xp = (float*)g_xproj4;
#pragma unroll
    for (int f = 0; f < 4; f++) {
        const int trow = tt * 128 + wm * 64 + f * 16 + (lane >> 2);
#pragma unroll
        for (int q = 0; q < 4; q++) {
            const int g = gt * 128 + wn * 32 + q * 8 + ((lane & 3) << 1);
            float2 bb = *(const float2*)&g_bias[g];
            float2 v0; v0.x = acc[f][q][0] + bb.x; v0.y = acc[f][q][1] + bb.y;
            float2 v1; v1.x = acc[f][q][2] + bb.x; v1.y = acc[f][q][3] + bb.y;
            *(float2*)&xp[((size_t)trow * BB + b) * GG + g]       = v0;
            *(float2*)&xp[((size_t)(trow + 8) * BB + b) * GG + g] = v1;
        }
    }
}

// ---------------------------------------------------------------------------
__device__ __forceinline__ void grid_sync()
{
    __syncthreads();
    if (threadIdx.x == 0) {
        __threadfence();
        unsigned gen = *(volatile unsigned*)&g_gen;
        if (atomicAdd(&g_cnt, 1) == gridDim.x - 1) {
            g_cnt = 0;
            __threadfence();
            atomicAdd(&g_gen, 1);
        } else {
            while (*(volatile unsigned*)&g_gen == gen) { }
        }
        __threadfence();
    }
    __syncthreads();
}

// ---------------------------------------------------------------------------
// Phase 2: persistent HMMA recurrent kernel, fp16 2-pass.
// CTA j owns h cols [8j,8j+8) => 32 gate cols g = q*1024 + 8j + nn.
// ---------------------------------------------------------------------------
#define SM_WHI 0
#define SM_A(buf, hl) (66048 + (buf)*36864 + (hl)*18432)
#define SM_TOT 139776

__global__ __launch_bounds__(256, 1) void lstm_mma_kernel(float* __restrict__ out)
{
    const int tx   = threadIdx.x;
    const int wid  = tx >> 5;
    const int lane = tx & 31;
    const int j    = blockIdx.x;
    const uint32_t sb = smem_u32(smem);

    // preload W slice (32 gate rows x 1024 fp16)
    {
        const __half* Whh = (const __half*)g_WhhH4;
        for (int idx = tx; idx < 32 * 128; idx += 256) {
            int row = idx >> 7, seg = idx & 127;
            int g = ((row >> 3) << 10) + (j << 3) + (row & 7);
            *(uint4*)(smem + SM_WHI + row * 2064 + seg * 16) =
                *(const uint4*)(Whh + (size_t)g * HH + seg * 8);
        }
    }

    float c[4] = {0.f, 0.f, 0.f, 0.f};

    const uint32_t aoff  = (uint32_t)((((wid << 4) + (lane & 15)) * 72 + ((lane >> 4) << 3)) * 2);
    const uint32_t wboff = (uint32_t)(((lane & 7) * 1032 + (((lane >> 3) & 1) << 3)) * 2);
    const uint32_t wb = sb + SM_WHI + wboff;

    const float* xpall = (const float*)g_xproj4;
    __syncthreads();

    for (int t = 0; t < TT; t++) {
        const __half* hhi = (const __half*)g_hbf4[t & 1][0];
        const __half* hlo = (const __half*)g_hbf4[t & 1][1];

        float acc[4][4];
#pragma unroll
        for (int q = 0; q < 4; q++)
#pragma unroll
            for (int e = 0; e < 4; e++) acc[q][e] = 0.f;

        {
            const int row = tx >> 3, seg = tx & 7;
#pragma unroll
            for (int r = 0; r < 4; r++) {
                int rr = row + (r << 5);
                uint32_t d = rr * 144 + seg * 16;
                CP16(sb + SM_A(0, 0) + d, hhi + rr * HH + (seg << 3));
                CP16(sb + SM_A(0, 1) + d, hlo + rr * HH + (seg << 3));
            }
            CP_COMMIT();
        }

        int buf = 0;
        for (int kt = 0; kt < 16; kt++) {
            if (kt < 15) {
                const int k0 = (kt + 1) << 6;
                const int row = tx >> 3, seg = tx & 7;
#pragma unroll
                for (int r = 0; r < 4; r++) {
                    int rr = row + (r << 5);
                    uint32_t d = rr * 144 + seg * 16;
                    CP16(sb + SM_A(buf ^ 1, 0) + d, hhi + rr * HH + k0 + (seg << 3));
                    CP16(sb + SM_A(buf ^ 1, 1) + d, hlo + rr * HH + k0 + (seg << 3));
                }
                CP_COMMIT();
                CP_WAIT1();
            } else {
                CP_WAIT0();
            }
            __syncthreads();

            const uint32_t aHi = sb + SM_A(buf, 0) + aoff;
            const uint32_t aLo = sb + SM_A(buf, 1) + aoff;
#pragma unroll
            for (int ks = 0; ks < 4; ks++) {
                uint32_t ah[4], al[4];
                LDSM4(ah, aHi + ks * 32);
                LDSM4(al, aLo + ks * 32);
                const uint32_t kcol = (uint32_t)(((kt << 6) + (ks << 4)) * 2);
#pragma unroll
                for (int q = 0; q < 4; q++) {
                    uint32_t bh[2];
                    LDSM2(bh, wb + q * 16512 + kcol);
                    MMA(acc[q], ah, bh);
                    MMA(acc[q], al, bh);
                }
            }
            __syncthreads();
            buf ^= 1;
        }

        // epilogue
        const int r0  = (wid << 4) + (lane >> 2);
        const int nn0 = (lane & 3) << 1;
        const float* xpt = xpall + (size_t)t * BB * GG;
        const int nb = (t + 1) & 1;
        __half* whi = (__half*)g_hbf4[nb][0];
        __half* wlo = (__half*)g_hbf4[nb][1];

#pragma unroll
        for (int rh = 0; rh < 2; rh++) {
            const int row = r0 + (rh << 3);
            const float* bp = xpt + (size_t)row * GG + (j << 3) + nn0;
            float2 xi = *(const float2*)(bp);
            float2 xf = *(const float2*)(bp + 1024);
            float2 xg = *(const float2*)(bp + 2048);
            float2 xo = *(const float2*)(bp + 3072);
            float hv[2];
#pragma unroll
            for (int e = 0; e < 2; e++) {
                const int p = (rh << 1) + e;
                float gi = acc[0][p] + (e ? xi.y : xi.x);
                float gf = acc[1][p] + (e ? xf.y : xf.x);
                float gg = acc[2][p] + (e ? xg.y : xg.x);
                float go = acc[3][p] + (e ? xo.y : xo.x);
                float iv = 1.f / (1.f + __expf(-gi));
                float fv = 1.f / (1.f + __expf(-gf));
                float gv = tanhf(gg);
                float ov = 1.f / (1.f + __expf(-go));
                float cv = fv * c[p] + iv * gv;
                c[p] = cv;
                hv[e] = ov * tanhf(cv);
            }
            __half a0 = __float2half_rn(hv[0]);
            __half a1 = __float2half_rn(hv[1]);
            __half l0 = __float2half_rn(hv[0] - __half2float(a0));
            __half l1 = __float2half_rn(hv[1] - __half2float(a1));
            uint32_t ph = (uint32_t)__half_as_ushort(a0) | ((uint32_t)__half_as_ushort(a1) << 16);
            uint32_t pl = (uint32_t)__half_as_ushort(l0) | ((uint32_t)__half_as_ushort(l1) << 16);
            *(uint32_t*)(whi + row * HH + (j << 3) + nn0) = ph;
            *(uint32_t*)(wlo + row * HH + (j << 3) + nn0) = pl;

            if (t == TT - 1) {
                float2 ov2; ov2.x = hv[0]; ov2.y = hv[1];
                *(float2*)(out + row * HH + (j << 3) + nn0) = ov2;
            }
        }
        grid_sync();
    }
}

// ---------------------------------------------------------------------------
extern "C" void kernel_launch(void* const* d_in, const int* in_sizes, int n_in,
                              void* d_out, int out_size)
{
    const float* x   = (const float*)d_in[0];
    const float* Wih = (const float*)d_in[1];
    const float* Whh = (const float*)d_in[2];
    const float* bih = (const float*)d_in[3];
    const float* bhh = (const float*)d_in[4];
    float* out = (float*)d_out;

    cudaFuncSetAttribute(lstm_mma_kernel, cudaFuncAttributeMaxDynamicSharedMemorySize, SM_TOT);
    cudaFuncSetAttribute(xproj_mma,       cudaFuncAttributeMaxDynamicSharedMemorySize, SMX_TOT);

    prep_whh<<<(int)(((size_t)GG * HH + 255) / 256), 256>>>(Whh);
    prep_wih<<<(int)(((size_t)GG * II + 255) / 256), 256>>>(Wih, bih, bhh);
    {
        dim3 g(TT / 32, II / 32, BB);
        dim3 bdim(32, 8);
        prep_x<<<g, bdim>>>(x);
    }
    {
        dim3 g(32, 2, BB);
        xproj_mma<<<g, 256, SMX_TOT>>>();
    }
    lstm_mma_kernel<<<128, 256, SM_TOT>>>(out);
}

// round 6
// speedup vs baseline: 4.7636x; 1.3650x over previous
#include <cuda_runtime.h>
#include <cuda_fp16.h>
#include <cstdint>
#include <math.h>

#define BB 128
#define II 512
#define TT 256
#define HH 1024
#define GG (4*HH)

// ---------------- scratch -----------------------------------------------
__device__ float4 g_xproj4[(size_t)TT * BB * GG / 4];       // [t][b][g] fp32
__device__ uint4  g_WhhH4[(size_t)GG * HH / 8];             // fp16 W_hh
__device__ uint4  g_WihH4[(size_t)GG * II / 8];             // fp16 W_ih
__device__ uint4  g_xT4[(size_t)BB * TT * II / 8];          // fp16 x^T [b][t][k]
__device__ uint4  g_hbf4[2][(size_t)BB * HH / 8];           // h fp16, double buffer
__device__ float  g_bias[GG];
__device__ unsigned g_cnt, g_gen;

// ---------------- helpers -----------------------------------------------
__device__ __forceinline__ uint32_t smem_u32(const void* p) {
    uint32_t a;
    asm("{ .reg .u64 t; cvta.to.shared.u64 t, %1; cvt.u32.u64 %0, t; }" : "=r"(a) : "l"(p));
    return a;
}
#define CP16(sa, ga) \
    asm volatile("cp.async.cg.shared.global [%0], [%1], 16;" :: "r"(sa), "l"(ga) : "memory")
#define CP_COMMIT() asm volatile("cp.async.commit_group;" ::: "memory")
#define CP_WAIT1()  asm volatile("cp.async.wait_group 1;" ::: "memory")
#define CP_WAIT0()  asm volatile("cp.async.wait_group 0;" ::: "memory")

#define LDSM4(r, a) \
    asm volatile("ldmatrix.sync.aligned.m8n8.x4.shared.b16 {%0,%1,%2,%3}, [%4];" \
        : "=r"((r)[0]), "=r"((r)[1]), "=r"((r)[2]), "=r"((r)[3]) : "r"(a))
#define LDSM2(r, a) \
    asm volatile("ldmatrix.sync.aligned.m8n8.x2.shared.b16 {%0,%1}, [%2];" \
        : "=r"((r)[0]), "=r"((r)[1]) : "r"(a))
#define MMA(d, a, b) \
    asm volatile("mma.sync.aligned.m16n8k16.row.col.f32.f16.f16.f32 " \
        "{%0,%1,%2,%3}, {%4,%5,%6,%7}, {%8,%9}, {%0,%1,%2,%3};" \
        : "+f"((d)[0]), "+f"((d)[1]), "+f"((d)[2]), "+f"((d)[3]) \
        : "r"((a)[0]), "r"((a)[1]), "r"((a)[2]), "r"((a)[3]), "r"((b)[0]), "r"((b)[1]))

extern __shared__ char smem[];

// ---------------------------------------------------------------------------
// Prep kernels
// ---------------------------------------------------------------------------
__global__ void prep_whh(const float* __restrict__ Whh)
{
    size_t i = (size_t)blockIdx.x * blockDim.x + threadIdx.x;
    if (i < (size_t)GG * HH)
        ((__half*)g_WhhH4)[i] = __float2half_rn(Whh[i]);
    if (i < (size_t)BB * HH) {
        ((__half*)g_hbf4[0])[i] = __float2half(0.f);
    }
}
__global__ void prep_wih(const float* __restrict__ Wih,
                         const float* __restrict__ bih,
                         const float* __restrict__ bhh)
{
    size_t i = (size_t)blockIdx.x * blockDim.x + threadIdx.x;
    if (i < (size_t)GG * II)
        ((__half*)g_WihH4)[i] = __float2half_rn(Wih[i]);
    if (i < GG)
        g_bias[i] = bih[i] + bhh[i];
}
// transpose: x[b][k][t] -> xT[b][t][k] fp16
__global__ void prep_x(const float* __restrict__ x)
{
    __shared__ float s[32][33];
    const int b = blockIdx.z, k0 = blockIdx.y * 32, t0 = blockIdx.x * 32;
    const int tx = threadIdx.x, ty = threadIdx.y;   // 32 x 8
    const float* xb = x + (size_t)b * II * TT;
#pragma unroll
    for (int i = 0; i < 4; i++)
        s[ty + 8 * i][tx] = xb[(size_t)(k0 + ty + 8 * i) * TT + t0 + tx];
    __syncthreads();
    __half* xh = (__half*)g_xT4;
    const size_t base = (size_t)b * TT * II;
#pragma unroll
    for (int i = 0; i < 4; i++) {
        float v = s[tx][ty + 8 * i];
        xh[base + (size_t)(t0 + ty + 8 * i) * II + k0 + tx] = __float2half_rn(v);
    }
}

// ---------------------------------------------------------------------------
// Phase 1: xproj via HMMA fp16 single-pass.
// A = xT[b][t][k] (M = t), B = W_ih[g][k] (N = g). Tiles 128x128, K=512.
// ---------------------------------------------------------------------------
#define SMX_A(bf) ((bf)*36864)
#define SMX_B(bf) ((bf)*36864 + 18432)
#define SMX_TOT 73728

__global__ __launch_bounds__(256, 2) void xproj_mma(void)
{
    const int tx = threadIdx.x, wid = tx >> 5, lane = tx & 31;
    const int gt = blockIdx.x;   // g tile 0..31
    const int tt = blockIdx.y;   // t tile 0..1
    const int b  = blockIdx.z;
    const uint32_t sb = smem_u32(smem);
    const int wm = wid & 1, wn = wid >> 1;

    const __half* xh = (const __half*)g_xT4 + (size_t)b * TT * II + (size_t)tt * 128 * II;
    const __half* Wh = (const __half*)g_WihH4 + (size_t)gt * 128 * II;

    float acc[4][4][4];
#pragma unroll
    for (int f = 0; f < 4; f++)
#pragma unroll
        for (int q = 0; q < 4; q++)
#pragma unroll
            for (int e = 0; e < 4; e++) acc[f][q][e] = 0.f;

    const int srow = tx >> 3, sseg = tx & 7;

    // prologue: chunk 0 -> buf 0
#pragma unroll
    for (int r = 0; r < 4; r++) {
        int row = srow + (r << 5);
        uint32_t d = row * 144 + sseg * 16;
        CP16(sb + SMX_A(0) + d, xh + (size_t)row * II + (sseg << 3));
        CP16(sb + SMX_B(0) + d, Wh + (size_t)row * II + (sseg << 3));
    }
    CP_COMMIT();

    int buf = 0;
    for (int kc = 0; kc < 8; kc++) {
        if (kc < 7) {
            const int k0 = (kc + 1) << 6;
#pragma unroll
            for (int r = 0; r < 4; r++) {
                int row = srow + (r << 5);
                uint32_t d = row * 144 + sseg * 16;
                CP16(sb + SMX_A(buf ^ 1) + d, xh + (size_t)row * II + k0 + (sseg << 3));
                CP16(sb + SMX_B(buf ^ 1) + d, Wh + (size_t)row * II + k0 + (sseg << 3));
            }
            CP_COMMIT();
            CP_WAIT1();
        } else {
            CP_WAIT0();
        }
        __syncthreads();

        const uint32_t aoff = (uint32_t)(((lane & 15) * 72 + ((lane >> 4) << 3)) * 2) + wm * 9216;
        const uint32_t aA = sb + SMX_A(buf) + aoff;
        const uint32_t bB = sb + SMX_B(buf) + wn * 4608
                          + (uint32_t)(((lane & 7) * 72 + (((lane >> 3) & 1) << 3)) * 2);
#pragma unroll
        for (int ks = 0; ks < 4; ks++) {
            uint32_t bh[4][2];
#pragma unroll
            for (int q = 0; q < 4; q++)
                LDSM2(bh[q], bB + q * 1152 + ks * 32);
#pragma unroll
            for (int f = 0; f < 4; f++) {
                uint32_t ah[4];
                LDSM4(ah, aA + f * 2304 + ks * 32);
#pragma unroll
                for (int q = 0; q < 4; q++)
                    MMA(acc[f][q], ah, bh[q]);
            }
        }
        __syncthreads();
        buf ^= 1;
    }

    // epilogue: += bias, store to xp[t][b][g]
    float* xp = (float*)g_xproj4;
#pragma unroll
    for (int f = 0; f < 4; f++) {
        const int trow = tt * 128 + wm * 64 + f * 16 + (lane >> 2);
#pragma unroll
        for (int q = 0; q < 4; q++) {
            const int g = gt * 128 + wn * 32 + q * 8 + ((lane & 3) << 1);
            float2 bb = *(const float2*)&g_bias[g];
            float2 v0; v0.x = acc[f][q][0] + bb.x; v0.y = acc[f][q][1] + bb.y;
            float2 v1; v1.x = acc[f][q][2] + bb.x; v1.y = acc[f][q][3] + bb.y;
            *(float2*)&xp[((size_t)trow * BB + b) * GG + g]       = v0;
            *(float2*)&xp[((size_t)(trow + 8) * BB + b) * GG + g] = v1;
        }
    }
}

// ---------------------------------------------------------------------------
__device__ __forceinline__ void grid_sync()
{
    __syncthreads();
    if (threadIdx.x == 0) {
        __threadfence();
        unsigned gen = *(volatile unsigned*)&g_gen;
        if (atomicAdd(&g_cnt, 1) == gridDim.x - 1) {
            g_cnt = 0;
            __threadfence();
            atomicAdd(&g_gen, 1);
        } else {
            while (*(volatile unsigned*)&g_gen == gen) { }
        }
        __threadfence();
    }
    __syncthreads();
}

// ---------------------------------------------------------------------------
// Phase 2: persistent HMMA recurrent kernel, fp16 single-pass.
// CTA j owns h cols [8j,8j+8) => 32 gate cols g = q*1024 + 8j + nn.
// ---------------------------------------------------------------------------
#define SM_WHI 0
#define SM_A(buf) (66048 + (buf)*18432)
#define SM_TOT (66048 + 36864)

__global__ __launch_bounds__(256, 1) void lstm_mma_kernel(float* __restrict__ out)
{
    const int tx   = threadIdx.x;
    const int wid  = tx >> 5;
    const int lane = tx & 31;
    const int j    = blockIdx.x;
    const uint32_t sb = smem_u32(smem);

    // preload W slice (32 gate rows x 1024 fp16)
    {
        const __half* Whh = (const __half*)g_WhhH4;
        for (int idx = tx; idx < 32 * 128; idx += 256) {
            int row = idx >> 7, seg = idx & 127;
            int g = ((row >> 3) << 10) + (j << 3) + (row & 7);
            *(uint4*)(smem + SM_WHI + row * 2064 + seg * 16) =
                *(const uint4*)(Whh + (size_t)g * HH + seg * 8);
        }
    }

    float c[4] = {0.f, 0.f, 0.f, 0.f};

    const uint32_t aoff  = (uint32_t)((((wid << 4) + (lane & 15)) * 72 + ((lane >> 4) << 3)) * 2);
    const uint32_t wboff = (uint32_t)(((lane & 7) * 1032 + (((lane >> 3) & 1) << 3)) * 2);
    const uint32_t wb = sb + SM_WHI + wboff;

    const float* xpall = (const float*)g_xproj4;
    __syncthreads();

    for (int t = 0; t < TT; t++) {
        const __half* hcur = (const __half*)g_hbf4[t & 1];

        float acc[4][4];
#pragma unroll
        for (int q = 0; q < 4; q++)
#pragma unroll
            for (int e = 0; e < 4; e++) acc[q][e] = 0.f;

        // prologue: stage k-tile 0 into buf 0 (128 rows x 64 halves)
        {
            const int row = tx >> 1, seg = tx & 1;   // 2 x uint4 segs of 8 halves.. (row 0..127, seg 0..1)
#pragma unroll
            for (int r = 0; r < 2; r++) {
                // 256 threads x 2 = 512 cp of 16B = 8192B? need 16384B -> 4 per thread
            }
        }
        // (re-done properly below)
        {
            const int row = tx >> 3, seg = tx & 7;   // row 0..31 base, seg 0..7
#pragma unroll
            for (int r = 0; r < 4; r++) {
                int rr = row + (r << 5);
                uint32_t d = rr * 144 + seg * 16;
                CP16(sb + SM_A(0) + d, hcur + rr * HH + (seg << 3));
            }
            CP_COMMIT();
        }

        int buf = 0;
        for (int kt = 0; kt < 16; kt++) {
            if (kt < 15) {
                const int k0 = (kt + 1) << 6;
                const int row = tx >> 3, seg = tx & 7;
#pragma unroll
                for (int r = 0; r < 4; r++) {
                    int rr = row + (r << 5);
                    uint32_t d = rr * 144 + seg * 16;
                    CP16(sb + SM_A(buf ^ 1) + d, hcur + rr * HH + k0 + (seg << 3));
                }
                CP_COMMIT();
                CP_WAIT1();
            } else {
                CP_WAIT0();
            }
            __syncthreads();

            const uint32_t aA = sb + SM_A(buf) + aoff;
#pragma unroll
            for (int ks = 0; ks < 4; ks++) {
                uint32_t ah[4];
                LDSM4(ah, aA + ks * 32);
                const uint32_t kcol = (uint32_t)(((kt << 6) + (ks << 4)) * 2);
#pragma unroll
                for (int q = 0; q < 4; q++) {
                    uint32_t bh[2];
                    LDSM2(bh, wb + q * 16512 + kcol);
                    MMA(acc[q], ah, bh);
                }
            }
            __syncthreads();
            buf ^= 1;
        }

        // epilogue
        const int r0  = (wid << 4) + (lane >> 2);
        const int nn0 = (lane & 3) << 1;
        const float* xpt = xpall + (size_t)t * BB * GG;
        __half* hnext = (__half*)g_hbf4[(t + 1) & 1];

#pragma unroll
        for (int rh = 0; rh < 2; rh++) {
            const int row = r0 + (rh << 3);
            const float* bp = xpt + (size_t)row * GG + (j << 3) + nn0;
            float2 xi = *(const float2*)(bp);
            float2 xf = *(const float2*)(bp + 1024);
            float2 xg = *(const float2*)(bp + 2048);
            float2 xo = *(const float2*)(bp + 3072);
            float hv[2];
#pragma unroll
            for (int e = 0; e < 2; e++) {
                const int p = (rh << 1) + e;
                float gi = acc[0][p] + (e ? xi.y : xi.x);
                float gf = acc[1][p] + (e ? xf.y : xf.x);
                float gg = acc[2][p] + (e ? xg.y : xg.x);
                float go = acc[3][p] + (e ? xo.y : xo.x);
                float iv = 1.f / (1.f + __expf(-gi));
                float fv = 1.f / (1.f + __expf(-gf));
                float gv = tanhf(gg);
                float ov = 1.f / (1.f + __expf(-go));
                float cv = fv * c[p] + iv * gv;
                c[p] = cv;
                hv[e] = ov * tanhf(cv);
            }
            __half a0 = __float2half_rn(hv[0]);
            __half a1 = __float2half_rn(hv[1]);
            uint32_t ph = (uint32_t)__half_as_ushort(a0) | ((uint32_t)__half_as_ushort(a1) << 16);
            *(uint32_t*)(hnext + row * HH + (j << 3) + nn0) = ph;

            if (t == TT - 1) {
                float2 ov2; ov2.x = hv[0]; ov2.y = hv[1];
                *(float2*)(out + row * HH + (j << 3) + nn0) = ov2;
            }
        }
        grid_sync();
    }
}

// ---------------------------------------------------------------------------
extern "C" void kernel_launch(void* const* d_in, const int* in_sizes, int n_in,
                              void* d_out, int out_size)
{
    const float* x   = (const float*)d_in[0];
    const float* Wih = (const float*)d_in[1];
    const float* Whh = (const float*)d_in[2];
    const float* bih = (const float*)d_in[3];
    const float* bhh = (const float*)d_in[4];
    float* out = (float*)d_out;

    cudaFuncSetAttribute(lstm_mma_kernel, cudaFuncAttributeMaxDynamicSharedMemorySize, SM_TOT);
    cudaFuncSetAttribute(xproj_mma,       cudaFuncAttributeMaxDynamicSharedMemorySize, SMX_TOT);

    prep_whh<<<(int)(((size_t)GG * HH + 255) / 256), 256>>>(Whh);
    prep_wih<<<(int)(((size_t)GG * II + 255) / 256), 256>>>(Wih, bih, bhh);
    {
        dim3 g(TT / 32, II / 32, BB);
        dim3 bdim(32, 8);
        prep_x<<<g, bdim>>>(x);
    }
    {
        dim3 g(32, 2, BB);
        xproj_mma<<<g, 256, SMX_TOT>>>();
    }
    lstm_mma_kernel<<<128, 256, SM_TOT>>>(out);
}